// round 14
// baseline (speedup 1.0000x reference)
#include <cuda_runtime.h>
#include <cuda_bf16.h>
#include <stdint.h>
#include <math.h>

#define N_ROUTES 7
#define PC_DIM   512
#define MC_DIM   128
#define KCLS     25
#define BSZ      4096
#define COLS     (KCLS * MC_DIM)        // 3200
#define VOTE_PER_B (N_ROUTES * COLS)    // 22400
#define PP_STRIDE (N_ROUTES * PC_DIM)   // 3584

__device__ short g_vote_i[(size_t)BSZ * VOTE_PER_B];                  // 184 MB
__device__ float g_vscale[(size_t)BSZ * N_ROUTES * KCLS];             // 2.9 MB
__device__ __nv_bfloat16 g_Phi[(size_t)BSZ * PP_STRIDE];
__device__ __nv_bfloat16 g_Plo[(size_t)BSZ * PP_STRIDE];
__device__ __nv_bfloat16 g_Whi[(size_t)N_ROUTES * COLS * PC_DIM];     // [n][col][d]
__device__ __nv_bfloat16 g_Wlo[(size_t)N_ROUTES * COLS * PC_DIM];

__device__ __forceinline__ uint32_t smem_to_u32(const void* p) {
    uint32_t a;
    asm("{ .reg .u64 t; cvta.to.shared.u64 t, %1; cvt.u32.u64 %0, t; }"
        : "=r"(a) : "l"(p));
    return a;
}
__device__ __forceinline__ uint32_t usw64(uint32_t o) {     // SW64 swizzle
    return o ^ ((o >> 3) & 0x30);
}

#define CP_ASYNC(sa, ga) \
    asm volatile("cp.async.cg.shared.global [%0], [%1], 16;" :: "r"(sa), "l"(ga))
#define CP_COMMIT() asm volatile("cp.async.commit_group;" ::: "memory")
#define CP_WAIT(N)  asm volatile("cp.async.wait_group %0;" :: "n"(N))

// ---------------------------------------------------------------------------
// Prep 1: split prim_pose into bf16 hi/lo
// ---------------------------------------------------------------------------
__global__ __launch_bounds__(512) void prep_p_kernel(const float* __restrict__ P) {
    size_t i = (size_t)blockIdx.x * 512 + threadIdx.x;   // float4 index
    float4 x = ((const float4*)P)[i];
    __nv_bfloat16 h0 = __float2bfloat16(x.x);
    __nv_bfloat16 h1 = __float2bfloat16(x.y);
    __nv_bfloat16 h2 = __float2bfloat16(x.z);
    __nv_bfloat16 h3 = __float2bfloat16(x.w);
    __nv_bfloat162* dh = (__nv_bfloat162*)g_Phi;
    __nv_bfloat162* dl = (__nv_bfloat162*)g_Plo;
    dh[2 * i]     = __nv_bfloat162(h0, h1);
    dh[2 * i + 1] = __nv_bfloat162(h2, h3);
    dl[2 * i] = __nv_bfloat162(__float2bfloat16(x.x - __bfloat162float(h0)),
                               __float2bfloat16(x.y - __bfloat162float(h1)));
    dl[2 * i + 1] = __nv_bfloat162(__float2bfloat16(x.z - __bfloat162float(h2)),
                                   __float2bfloat16(x.w - __bfloat162float(h3)));
}

// ---------------------------------------------------------------------------
// Prep 2: transpose+split W[n][d][col] -> Whi/Wlo [n][col][d]
// ---------------------------------------------------------------------------
__global__ __launch_bounds__(256) void prep_w_kernel(const float* __restrict__ W) {
    __shared__ float tile[32][33];
    const int n = blockIdx.z;
    const int c0 = blockIdx.x * 32;
    const int d0 = blockIdx.y * 32;
    const float* Wn = W + (size_t)n * PC_DIM * COLS;
#pragma unroll
    for (int j = 0; j < 4; j++) {
        int d = d0 + threadIdx.y + j * 8;
        tile[threadIdx.y + j * 8][threadIdx.x] = Wn[(size_t)d * COLS + c0 + threadIdx.x];
    }
    __syncthreads();
#pragma unroll
    for (int j = 0; j < 4; j++) {
        int col = c0 + threadIdx.y + j * 8;
        int d = d0 + threadIdx.x;
        float x = tile[threadIdx.x][threadIdx.y + j * 8];
        __nv_bfloat16 h = __float2bfloat16(x);
        size_t o = ((size_t)n * COLS + col) * PC_DIM + d;
        g_Whi[o] = h;
        g_Wlo[o] = __float2bfloat16(x - __bfloat162float(h));
    }
}

// ---------------------------------------------------------------------------
// Vote GEMM (R10 mainloop): mma.sync bf16 3-term split. CTA 128x128, 8 warps
// (4 wm x 2 wn, warp tile 32x64). KCH=32, SW64 smem, 3-stage cp.async.
// Epilogue: per-(row, capsule) max -> int16 quantized store + fp32 scale.
// ---------------------------------------------------------------------------
#define KCH 32
#define T_AH 0
#define T_AL 8192
#define T_BH 16384
#define T_BL 24576
#define STG_BYTES 32768
#define NSTG 3
#define GEMM_SMEM (NSTG * STG_BYTES)      // 98304 -> 2 CTAs/SM
#define NC (PC_DIM / KCH)                 // 16

#define LDSM_X4(r0, r1, r2, r3, a) \
    asm volatile("ldmatrix.sync.aligned.m8n8.x4.shared.b16 {%0,%1,%2,%3}, [%4];" \
        : "=r"(r0), "=r"(r1), "=r"(r2), "=r"(r3) : "r"(a))

#define MMA_BF16(d, a, b0, b1) \
    asm volatile("mma.sync.aligned.m16n8k16.row.col.f32.bf16.bf16.f32 " \
        "{%0,%1,%2,%3}, {%4,%5,%6,%7}, {%8,%9}, {%0,%1,%2,%3};" \
        : "+f"((d)[0]), "+f"((d)[1]), "+f"((d)[2]), "+f"((d)[3]) \
        : "r"((a)[0]), "r"((a)[1]), "r"((a)[2]), "r"((a)[3]), "r"(b0), "r"(b1))

__global__ __launch_bounds__(256, 2) void vote_gemm_tc(void) {
    extern __shared__ char smem[];
    const uint32_t sb = smem_to_u32(smem);
    const int tid  = threadIdx.x;
    const int lane = tid & 31;
    const int warp = tid >> 5;
    const int wm   = warp & 3;          // M block of 32
    const int wn   = warp >> 2;         // N block of 64

    const int n  = blockIdx.z;
    const int mC = blockIdx.x;          // capsule index (128-col tile == capsule)
    const int bm = blockIdx.y * 128;
    const int bn = mC * 128;

    const __nv_bfloat16* Ahi = g_Phi + (size_t)bm * PP_STRIDE + (size_t)n * PC_DIM;
    const __nv_bfloat16* Alo = g_Plo + (size_t)bm * PP_STRIDE + (size_t)n * PC_DIM;
    const __nv_bfloat16* Bhi = g_Whi + ((size_t)n * COLS + bn) * PC_DIM;
    const __nv_bfloat16* Blo = g_Wlo + ((size_t)n * COLS + bn) * PC_DIM;

    float acc[2][8][4];
#pragma unroll
    for (int i = 0; i < 2; i++)
#pragma unroll
        for (int j = 0; j < 8; j++)
#pragma unroll
            for (int q = 0; q < 4; q++) acc[i][j][q] = 0.f;

    const int lrow = lane & 15, lch = lane >> 4;

    auto issue_stage = [&](int c, int buf) {
        const int k0 = c * KCH;
        const uint32_t sbase = sb + buf * STG_BYTES;
#pragma unroll
        for (int p = 0; p < 8; p++) {
            int id  = p * 256 + tid;
            int t   = id >> 9;          // 0..3
            int rem = id & 511;
            int row = rem >> 2;
            int ch  = rem & 3;
            uint32_t sa = sbase + t * 8192 + usw64(row * 64 + ch * 16);
            const __nv_bfloat16* g;
            if (t == 0)      g = Ahi + (size_t)row * PP_STRIDE + k0 + ch * 8;
            else if (t == 1) g = Alo + (size_t)row * PP_STRIDE + k0 + ch * 8;
            else if (t == 2) g = Bhi + (size_t)row * PC_DIM + k0 + ch * 8;
            else             g = Blo + (size_t)row * PC_DIM + k0 + ch * 8;
            CP_ASYNC(sa, g);
        }
        CP_COMMIT();
    };

    issue_stage(0, 0);
    issue_stage(1, 1);
    issue_stage(2, 2);

    for (int c = 0; c < NC; c++) {
        if (c <= NC - 3)      CP_WAIT(2);
        else if (c == NC - 2) CP_WAIT(1);
        else                  CP_WAIT(0);
        __syncthreads();

        const uint32_t sbase = sb + (c % 3) * STG_BYTES;
#pragma unroll
        for (int ks = 0; ks < 2; ks++) {
            const uint32_t kb = ks * 32 + lch * 16;
            uint32_t ah[2][4], al[2][4];
#pragma unroll
            for (int mt = 0; mt < 2; mt++) {
                uint32_t ao = usw64((wm * 32 + mt * 16 + lrow) * 64 + kb);
                LDSM_X4(ah[mt][0], ah[mt][1], ah[mt][2], ah[mt][3], sbase + T_AH + ao);
                LDSM_X4(al[mt][0], al[mt][1], al[mt][2], al[mt][3], sbase + T_AL + ao);
            }
#pragma unroll
            for (int g = 0; g < 4; g++) {
                uint32_t bo = usw64((wn * 64 + g * 16 + lrow) * 64 + kb);
                uint32_t bh[4], bl[4];
                LDSM_X4(bh[0], bh[1], bh[2], bh[3], sbase + T_BH + bo);
                LDSM_X4(bl[0], bl[1], bl[2], bl[3], sbase + T_BL + bo);
                MMA_BF16(acc[0][g * 2 + 0], ah[0], bh[0], bh[2]);
                MMA_BF16(acc[0][g * 2 + 1], ah[0], bh[1], bh[3]);
                MMA_BF16(acc[1][g * 2 + 0], ah[1], bh[0], bh[2]);
                MMA_BF16(acc[1][g * 2 + 1], ah[1], bh[1], bh[3]);
                MMA_BF16(acc[0][g * 2 + 0], ah[0], bl[0], bl[2]);
                MMA_BF16(acc[0][g * 2 + 1], ah[0], bl[1], bl[3]);
                MMA_BF16(acc[1][g * 2 + 0], ah[1], bl[0], bl[2]);
                MMA_BF16(acc[1][g * 2 + 1], ah[1], bl[1], bl[3]);
                MMA_BF16(acc[0][g * 2 + 0], al[0], bh[0], bh[2]);
                MMA_BF16(acc[0][g * 2 + 1], al[0], bh[1], bh[3]);
                MMA_BF16(acc[1][g * 2 + 0], al[1], bh[0], bh[2]);
                MMA_BF16(acc[1][g * 2 + 1], al[1], bh[1], bh[3]);
            }
        }
        __syncthreads();
        if (c + 3 < NC) issue_stage(c + 3, (c + 3) % 3);
    }

    // ---- epilogue: per-row abs-max over the capsule -> int16 quantize ----
    // Thread holds rows r0 = wm*32 + mt*16 + (lane>>2) and r0+8 (per mt).
    float rmax[2][2] = {{0.f, 0.f}, {0.f, 0.f}};
#pragma unroll
    for (int mt = 0; mt < 2; mt++)
#pragma unroll
        for (int j = 0; j < 8; j++) {
            rmax[mt][0] = fmaxf(rmax[mt][0],
                                fmaxf(fabsf(acc[mt][j][0]), fabsf(acc[mt][j][1])));
            rmax[mt][1] = fmaxf(rmax[mt][1],
                                fmaxf(fabsf(acc[mt][j][2]), fabsf(acc[mt][j][3])));
        }
#pragma unroll
    for (int o = 1; o <= 2; o <<= 1) {
#pragma unroll
        for (int mt = 0; mt < 2; mt++) {
            rmax[mt][0] = fmaxf(rmax[mt][0], __shfl_xor_sync(0xffffffffu, rmax[mt][0], o));
            rmax[mt][1] = fmaxf(rmax[mt][1], __shfl_xor_sync(0xffffffffu, rmax[mt][1], o));
        }
    }
    float* s_rmax = (float*)smem;       // [128][2], mainloop smem now free
    if ((lane & 3) == 0) {
#pragma unroll
        for (int mt = 0; mt < 2; mt++) {
            int r0 = wm * 32 + mt * 16 + (lane >> 2);
            s_rmax[r0 * 2 + wn]       = rmax[mt][0];
            s_rmax[(r0 + 8) * 2 + wn] = rmax[mt][1];
        }
    }
    __syncthreads();

#pragma unroll
    for (int mt = 0; mt < 2; mt++) {
        const int lr0 = wm * 32 + mt * 16 + (lane >> 2);
        const int lr1 = lr0 + 8;
        float sc0 = fmaxf(fmaxf(s_rmax[lr0 * 2], s_rmax[lr0 * 2 + 1]), 1e-30f);
        float sc1 = fmaxf(fmaxf(s_rmax[lr1 * 2], s_rmax[lr1 * 2 + 1]), 1e-30f);
        if (wn == 0 && (lane & 3) == 0) {
            g_vscale[((size_t)(bm + lr0) * N_ROUTES + n) * KCLS + mC] = sc0;
            g_vscale[((size_t)(bm + lr1) * N_ROUTES + n) * KCLS + mC] = sc1;
        }
        const float q0 = 32767.f / sc0, q1 = 32767.f / sc1;
#pragma unroll
        for (int j = 0; j < 8; j++) {
            int g = j >> 1, nt = j & 1;
            int col = wn * 64 + g * 16 + nt * 8 + (lane & 3) * 2;
            short* d0 = g_vote_i + (size_t)(bm + lr0) * VOTE_PER_B
                        + (size_t)n * COLS + bn + col;
            short* d1 = g_vote_i + (size_t)(bm + lr1) * VOTE_PER_B
                        + (size_t)n * COLS + bn + col;
            short2 o0, o1;
            o0.x = (short)__float2int_rn(acc[mt][j][0] * q0);
            o0.y = (short)__float2int_rn(acc[mt][j][1] * q0);
            o1.x = (short)__float2int_rn(acc[mt][j][2] * q1);
            o1.y = (short)__float2int_rn(acc[mt][j][3] * q1);
            *(short2*)d0 = o0;
            *(short2*)d1 = o1;
        }
    }
}

// ---------------------------------------------------------------------------
// Persistent routing: 148 CTAs, 800 threads (warp = capsule m). int16 votes,
// 3 smem buffers (44.8 KB each) -> 2-row-deep cp.async prefetch.
// ---------------------------------------------------------------------------
#define ROUT_GRID 148
#define ROW_SHORTS VOTE_PER_B                    // 22400 shorts = 44800 B
#define ROW_BYTES (ROW_SHORTS * 2)
#define ROW_CHUNKS (ROW_BYTES / 16)              // 2800
#define NBUF 3
#define ROUT_SMEM (NBUF * ROW_BYTES)             // 134400 bytes

__device__ __forceinline__ float warp_sum(float v) {
#pragma unroll
    for (int o = 16; o; o >>= 1) v += __shfl_xor_sync(0xffffffffu, v, o);
    return v;
}
__device__ __forceinline__ float warp_max32(float v) {
#pragma unroll
    for (int o = 16; o; o >>= 1) v = fmaxf(v, __shfl_xor_sync(0xffffffffu, v, o));
    return v;
}
__device__ __forceinline__ void warp_sum2(float& a, float& b) {
#pragma unroll
    for (int o = 16; o; o >>= 1) {
        a += __shfl_xor_sync(0xffffffffu, a, o);
        b += __shfl_xor_sync(0xffffffffu, b, o);
    }
}

__global__ __launch_bounds__(800, 1) void routing_kernel(
    const float* __restrict__ prim_act,
    const float* __restrict__ ln_gamma, const float* __restrict__ ln_beta,
    const float* __restrict__ embedding, const float* __restrict__ bias,
    float* __restrict__ out_logits, float* __restrict__ out_act,
    float* __restrict__ out_coef) {
    extern __shared__ short s_vote[];            // NBUF x 22400 shorts
    __shared__ float s_agree[N_ROUTES * KCLS];
    __shared__ float s_coef[N_ROUTES * KCLS];

    const int tid  = threadIdx.x;
    const int lane = tid & 31;
    const int m    = tid >> 5;                   // warp id == capsule, 0..24
    const uint32_t sb = smem_to_u32(s_vote);

    const float4 g4 = ((const float4*)ln_gamma)[lane];
    const float4 b4 = ((const float4*)ln_beta)[lane];
    const float4 em = ((const float4*)(embedding + (size_t)m * MC_DIM))[lane];
    const float  bi = bias[m];

    // guarded prefetch: always commits (empty groups are legal)
    auto prefetch = [&](int row, int buf) {
        if (row < BSZ) {
            const uint4* src = (const uint4*)(g_vote_i + (size_t)row * ROW_SHORTS);
            const uint32_t dst = sb + buf * ROW_BYTES;
#pragma unroll
            for (int j = 0; j < 4; j++) {
                int idx = tid + j * 800;         // 2800 chunks
                if (idx < ROW_CHUNKS) CP_ASYNC(dst + idx * 16, src + idx);
            }
        }
        CP_COMMIT();
    };

    prefetch(blockIdx.x, 0);
    prefetch(blockIdx.x + ROUT_GRID, 1);

    int k = 0;
    for (int r = blockIdx.x; r < BSZ; r += ROUT_GRID, k++) {
        prefetch(r + 2 * ROUT_GRID, (k + 2) % NBUF);
        CP_WAIT(2);
        __syncthreads();

        float a_r[N_ROUTES];
#pragma unroll
        for (int nn = 0; nn < N_ROUTES; nn++)
            a_r[nn] = prim_act[(size_t)r * N_ROUTES + nn];

        // dequantize vote slice into registers
        float4 v[N_ROUTES];
        {
            const short* vb = s_vote + (k % NBUF) * ROW_SHORTS + m * MC_DIM + lane * 4;
            const float* scb = g_vscale + ((size_t)r * N_ROUTES) * KCLS + m;
#pragma unroll
            for (int nn = 0; nn < N_ROUTES; nn++) {
                short4 raw = *(const short4*)(vb + nn * COLS);
                float s = scb[nn * KCLS] * (1.f / 32767.f);
                v[nn] = make_float4(raw.x * s, raw.y * s, raw.z * s, raw.w * s);
            }
        }

        float4 p = make_float4(0.f, 0.f, 0.f, 0.f);
#pragma unroll
        for (int nn = 0; nn < N_ROUTES; nn++) {
            p.x += a_r[nn] * v[nn].x;
            p.y += a_r[nn] * v[nn].y;
            p.z += a_r[nn] * v[nn].z;
            p.w += a_r[nn] * v[nn].w;
        }
        p.x *= (1.f / 25.f); p.y *= (1.f / 25.f);
        p.z *= (1.f / 25.f); p.w *= (1.f / 25.f);

        auto layernorm = [&](float4& x) {
            float s1 = x.x + x.y + x.z + x.w;
            float s2 = x.x * x.x + x.y * x.y + x.z * x.z + x.w * x.w;
            warp_sum2(s1, s2);
            float mu = s1 * (1.f / MC_DIM);
            float ve = s2 * (1.f / MC_DIM) - mu * mu + 1e-5f;
            float rr = rsqrtf(ve);
            rr = rr * (1.5f - 0.5f * ve * rr * rr);
            x.x = (x.x - mu) * rr * g4.x + b4.x;
            x.y = (x.y - mu) * rr * g4.y + b4.y;
            x.z = (x.z - mu) * rr * g4.z + b4.z;
            x.w = (x.w - mu) * rr * g4.w + b4.w;
        };
        layernorm(p);

        const float scale = 0.08838834764831845f;   // 1/sqrt(128)
#pragma unroll
        for (int it = 1; it <= 2; it++) {
#pragma unroll
            for (int nn = 0; nn < N_ROUTES; nn++) {
                float d = v[nn].x * p.x + v[nn].y * p.y + v[nn].z * p.z + v[nn].w * p.w;
                d = warp_sum(d);
                if (lane == 0) s_agree[nn * KCLS + m] = d * scale;
            }
            __syncthreads();

            if (m < N_ROUTES) {
                float aval = (lane < KCLS) ? s_agree[m * KCLS + lane] : -1e30f;
                float mx = warp_max32(aval);
                float e = (lane < KCLS) ? expf(aval - mx) : 0.f;
                float s = warp_sum(e);
                if (lane < KCLS) s_coef[m * KCLS + lane] = e / s;
            }
            __syncthreads();

            if (it == 2 && tid < N_ROUTES * KCLS)
                out_coef[(size_t)r * (N_ROUTES * KCLS) + tid] = s_coef[tid];

            p = make_float4(0.f, 0.f, 0.f, 0.f);
#pragma unroll
            for (int nn = 0; nn < N_ROUTES; nn++) {
                float ca = s_coef[nn * KCLS + m] * a_r[nn];
                p.x += ca * v[nn].x;
                p.y += ca * v[nn].y;
                p.z += ca * v[nn].z;
                p.w += ca * v[nn].w;
            }
            layernorm(p);
            __syncthreads();
        }

        {
            float d = p.x * em.x + p.y * em.y + p.z * em.z + p.w * em.w;
            d = warp_sum(d);
            if (lane == 0) out_logits[(size_t)r * KCLS + m] = d + bi;
        }
        if (tid < N_ROUTES)
            out_act[(size_t)r * N_ROUTES + tid] = a_r[tid];
        // trailing barrier above (end of it-loop) orders buffer reads before
        // the next iteration's prefetch overwrites buffer (k+2)%NBUF.
    }
}

// ---------------------------------------------------------------------------
extern "C" void kernel_launch(void* const* d_in, const int* in_sizes, int n_in,
                              void* d_out, int out_size) {
    const float* prim_pose = (const float*)d_in[0];
    const float* prim_act  = (const float*)d_in[1];
    const float* w         = (const float*)d_in[2];
    const float* ln_gamma  = (const float*)d_in[3];
    const float* ln_beta   = (const float*)d_in[4];
    const float* embedding = (const float*)d_in[5];
    const float* bias      = (const float*)d_in[6];

    float* out        = (float*)d_out;
    float* out_logits = out;
    float* out_act    = out + (size_t)BSZ * KCLS;
    float* out_coef   = out_act + (size_t)BSZ * N_ROUTES;

    prep_p_kernel<<<(BSZ * PP_STRIDE) / 4 / 512, 512>>>(prim_pose);
    prep_w_kernel<<<dim3(COLS / 32, PC_DIM / 32, N_ROUTES), dim3(32, 8)>>>(w);

    cudaFuncSetAttribute(vote_gemm_tc,
                         cudaFuncAttributeMaxDynamicSharedMemorySize, GEMM_SMEM);
    dim3 g(COLS / 128, BSZ / 128, N_ROUTES);   // (25, 32, 7)
    vote_gemm_tc<<<g, 256, GEMM_SMEM>>>();

    cudaFuncSetAttribute(routing_kernel,
                         cudaFuncAttributeMaxDynamicSharedMemorySize, ROUT_SMEM);
    routing_kernel<<<ROUT_GRID, 800, ROUT_SMEM>>>(prim_act, ln_gamma, ln_beta,
                                                  embedding, bias,
                                                  out_logits, out_act, out_coef);
}

// round 15
// speedup vs baseline: 1.3692x; 1.3692x over previous
#include <cuda_runtime.h>
#include <cuda_fp16.h>
#include <stdint.h>
#include <math.h>

#define N_ROUTES 7
#define PC_DIM   512
#define MC_DIM   128
#define KCLS     25
#define BSZ      4096
#define COLS     (KCLS * MC_DIM)        // 3200
#define VOTE_PER_B (N_ROUTES * COLS)    // 22400
#define PP_STRIDE (N_ROUTES * PC_DIM)   // 3584

__device__ float g_vote[(size_t)BSZ * VOTE_PER_B];                    // 367 MB
__device__ __half g_Ph[(size_t)BSZ * PP_STRIDE];                      // P fp16
__device__ __half g_Whi[(size_t)N_ROUTES * COLS * PC_DIM];            // [n][col][d]
__device__ __half g_Wlo[(size_t)N_ROUTES * COLS * PC_DIM];

__device__ __forceinline__ uint32_t smem_to_u32(const void* p) {
    uint32_t a;
    asm("{ .reg .u64 t; cvta.to.shared.u64 t, %1; cvt.u32.u64 %0, t; }"
        : "=r"(a) : "l"(p));
    return a;
}
__device__ __forceinline__ uint32_t usw64(uint32_t o) {     // SW64 swizzle
    return o ^ ((o >> 3) & 0x30);
}

#define CP_ASYNC(sa, ga) \
    asm volatile("cp.async.cg.shared.global [%0], [%1], 16;" :: "r"(sa), "l"(ga))
#define CP_COMMIT() asm volatile("cp.async.commit_group;" ::: "memory")
#define CP_WAIT(N)  asm volatile("cp.async.wait_group %0;" :: "n"(N))

// ---------------------------------------------------------------------------
// Prep 1: prim_pose -> fp16 (single digit)
// ---------------------------------------------------------------------------
__global__ __launch_bounds__(512) void prep_p_kernel(const float* __restrict__ P) {
    size_t i = (size_t)blockIdx.x * 512 + threadIdx.x;   // float4 index
    float4 x = ((const float4*)P)[i];
    __half2* dh = (__half2*)g_Ph;
    dh[2 * i]     = __halves2half2(__float2half(x.x), __float2half(x.y));
    dh[2 * i + 1] = __halves2half2(__float2half(x.z), __float2half(x.w));
}

// ---------------------------------------------------------------------------
// Prep 2: transpose+split W[n][d][col] -> Whi/Wlo [n][col][d] (fp16 digits)
// ---------------------------------------------------------------------------
__global__ __launch_bounds__(256) void prep_w_kernel(const float* __restrict__ W) {
    __shared__ float tile[32][33];
    const int n = blockIdx.z;
    const int c0 = blockIdx.x * 32;
    const int d0 = blockIdx.y * 32;
    const float* Wn = W + (size_t)n * PC_DIM * COLS;
#pragma unroll
    for (int j = 0; j < 4; j++) {
        int d = d0 + threadIdx.y + j * 8;
        tile[threadIdx.y + j * 8][threadIdx.x] = Wn[(size_t)d * COLS + c0 + threadIdx.x];
    }
    __syncthreads();
#pragma unroll
    for (int j = 0; j < 4; j++) {
        int col = c0 + threadIdx.y + j * 8;
        int d = d0 + threadIdx.x;
        float x = tile[threadIdx.x][threadIdx.y + j * 8];
        __half h = __float2half(x);
        size_t o = ((size_t)n * COLS + col) * PC_DIM + d;
        g_Whi[o] = h;
        g_Wlo[o] = __float2half(x - __half2float(h));
    }
}

// ---------------------------------------------------------------------------
// Vote GEMM: P fp16 x (Whi + Wlo) = 2 MMAs per step (was 3). CTA 128x128,
// 8 warps (4 wm x 2 wn, warp tile 32x64). KCH=32, SW64 smem, 3-stage cp.async.
// ---------------------------------------------------------------------------
#define KCH 32
#define T_A  0
#define T_BH 8192
#define T_BL 16384
#define STG_BYTES 24576
#define NSTG 3
#define GEMM_SMEM (NSTG * STG_BYTES)      // 73728 -> 2 CTAs/SM
#define NC (PC_DIM / KCH)                 // 16

#define LDSM_X4(r0, r1, r2, r3, a) \
    asm volatile("ldmatrix.sync.aligned.m8n8.x4.shared.b16 {%0,%1,%2,%3}, [%4];" \
        : "=r"(r0), "=r"(r1), "=r"(r2), "=r"(r3) : "r"(a))

#define MMA_F16(d, a, b0, b1) \
    asm volatile("mma.sync.aligned.m16n8k16.row.col.f32.f16.f16.f32 " \
        "{%0,%1,%2,%3}, {%4,%5,%6,%7}, {%8,%9}, {%0,%1,%2,%3};" \
        : "+f"((d)[0]), "+f"((d)[1]), "+f"((d)[2]), "+f"((d)[3]) \
        : "r"((a)[0]), "r"((a)[1]), "r"((a)[2]), "r"((a)[3]), "r"(b0), "r"(b1))

__global__ __launch_bounds__(256, 2) void vote_gemm_tc(void) {
    extern __shared__ char smem[];
    const uint32_t sb = smem_to_u32(smem);
    const int tid  = threadIdx.x;
    const int lane = tid & 31;
    const int warp = tid >> 5;
    const int wm   = warp & 3;          // M block of 32
    const int wn   = warp >> 2;         // N block of 64

    const int n  = blockIdx.z;
    const int bm = blockIdx.y * 128;
    const int bn = blockIdx.x * 128;

    const __half* A   = g_Ph  + (size_t)bm * PP_STRIDE + (size_t)n * PC_DIM;
    const __half* Bhi = g_Whi + ((size_t)n * COLS + bn) * PC_DIM;
    const __half* Blo = g_Wlo + ((size_t)n * COLS + bn) * PC_DIM;

    float acc[2][8][4];
#pragma unroll
    for (int i = 0; i < 2; i++)
#pragma unroll
        for (int j = 0; j < 8; j++)
#pragma unroll
            for (int q = 0; q < 4; q++) acc[i][j][q] = 0.f;

    const int lrow = lane & 15, lch = lane >> 4;

    // 1536 16B-chunks/stage, 6 per thread; t = 0:A, 1:Bh, 2:Bl
    auto issue_stage = [&](int c, int buf) {
        const int k0 = c * KCH;
        const uint32_t sbase = sb + buf * STG_BYTES;
#pragma unroll
        for (int p = 0; p < 6; p++) {
            int id  = p * 256 + tid;
            int t   = id >> 9;          // 0..2
            int rem = id & 511;
            int row = rem >> 2;
            int ch  = rem & 3;
            uint32_t sa = sbase + t * 8192 + usw64(row * 64 + ch * 16);
            const __half* g;
            if (t == 0)      g = A   + (size_t)row * PP_STRIDE + k0 + ch * 8;
            else if (t == 1) g = Bhi + (size_t)row * PC_DIM + k0 + ch * 8;
            else             g = Blo + (size_t)row * PC_DIM + k0 + ch * 8;
            CP_ASYNC(sa, g);
        }
        CP_COMMIT();
    };

    issue_stage(0, 0);
    issue_stage(1, 1);
    issue_stage(2, 2);

    for (int c = 0; c < NC; c++) {
        if (c <= NC - 3)      CP_WAIT(2);
        else if (c == NC - 2) CP_WAIT(1);
        else                  CP_WAIT(0);
        __syncthreads();

        const uint32_t sbase = sb + (c % 3) * STG_BYTES;
#pragma unroll
        for (int ks = 0; ks < 2; ks++) {
            const uint32_t kb = ks * 32 + lch * 16;
            uint32_t ah[2][4];
#pragma unroll
            for (int mt = 0; mt < 2; mt++) {
                uint32_t ao = usw64((wm * 32 + mt * 16 + lrow) * 64 + kb);
                LDSM_X4(ah[mt][0], ah[mt][1], ah[mt][2], ah[mt][3], sbase + T_A + ao);
            }
#pragma unroll
            for (int g = 0; g < 4; g++) {
                uint32_t bo = usw64((wn * 64 + g * 16 + lrow) * 64 + kb);
                uint32_t bh[4], bl[4];
                LDSM_X4(bh[0], bh[1], bh[2], bh[3], sbase + T_BH + bo);
                LDSM_X4(bl[0], bl[1], bl[2], bl[3], sbase + T_BL + bo);
                // term A x Bh
                MMA_F16(acc[0][g * 2 + 0], ah[0], bh[0], bh[2]);
                MMA_F16(acc[0][g * 2 + 1], ah[0], bh[1], bh[3]);
                MMA_F16(acc[1][g * 2 + 0], ah[1], bh[0], bh[2]);
                MMA_F16(acc[1][g * 2 + 1], ah[1], bh[1], bh[3]);
                // term A x Bl (same accs, distance 4 — proven adequate)
                MMA_F16(acc[0][g * 2 + 0], ah[0], bl[0], bl[2]);
                MMA_F16(acc[0][g * 2 + 1], ah[0], bl[1], bl[3]);
                MMA_F16(acc[1][g * 2 + 0], ah[1], bl[0], bl[2]);
                MMA_F16(acc[1][g * 2 + 1], ah[1], bl[1], bl[3]);
            }
        }
        __syncthreads();
        if (c + 3 < NC) issue_stage(c + 3, (c + 3) % 3);
    }

    // epilogue: direct fp32 stores
#pragma unroll
    for (int mt = 0; mt < 2; mt++) {
#pragma unroll
        for (int j = 0; j < 8; j++) {
            int g = j >> 1, nt = j & 1;
            int row = bm + wm * 32 + mt * 16 + (lane >> 2);
            int col = bn + wn * 64 + g * 16 + nt * 8 + (lane & 3) * 2;
            float* d0 = g_vote + (size_t)row * VOTE_PER_B + (size_t)n * COLS + col;
            float* d1 = d0 + (size_t)8 * VOTE_PER_B;
            *(float2*)d0 = make_float2(acc[mt][j][0], acc[mt][j][1]);
            *(float2*)d1 = make_float2(acc[mt][j][2], acc[mt][j][3]);
        }
    }
}

// ---------------------------------------------------------------------------
// Persistent routing (R10, proven): 296 CTAs, 800 threads, double-buffered
// cp.async fp32 vote prefetch. Warp = capsule m.
// ---------------------------------------------------------------------------
#define ROUT_GRID 296
#define ROW_FLOATS VOTE_PER_B                    // 22400
#define ROUT_SMEM (2 * ROW_FLOATS * 4)           // 179200 bytes

__device__ __forceinline__ float warp_sum(float v) {
#pragma unroll
    for (int o = 16; o; o >>= 1) v += __shfl_xor_sync(0xffffffffu, v, o);
    return v;
}
__device__ __forceinline__ float warp_max32(float v) {
#pragma unroll
    for (int o = 16; o; o >>= 1) v = fmaxf(v, __shfl_xor_sync(0xffffffffu, v, o));
    return v;
}
__device__ __forceinline__ void warp_sum2(float& a, float& b) {
#pragma unroll
    for (int o = 16; o; o >>= 1) {
        a += __shfl_xor_sync(0xffffffffu, a, o);
        b += __shfl_xor_sync(0xffffffffu, b, o);
    }
}

__global__ __launch_bounds__(800, 1) void routing_kernel(
    const float* __restrict__ prim_act,
    const float* __restrict__ ln_gamma, const float* __restrict__ ln_beta,
    const float* __restrict__ embedding, const float* __restrict__ bias,
    float* __restrict__ out_logits, float* __restrict__ out_act,
    float* __restrict__ out_coef) {
    extern __shared__ float s_vote[];            // 2 x 22400 floats
    __shared__ float s_agree[N_ROUTES * KCLS];
    __shared__ float s_coef[N_ROUTES * KCLS];

    const int tid  = threadIdx.x;
    const int lane = tid & 31;
    const int m    = tid >> 5;                   // warp id == capsule, 0..24
    const uint32_t sb = smem_to_u32(s_vote);

    const float4 g4 = ((const float4*)ln_gamma)[lane];
    const float4 b4 = ((const float4*)ln_beta)[lane];
    const float4 em = ((const float4*)(embedding + (size_t)m * MC_DIM))[lane];
    const float  bi = bias[m];

    auto prefetch = [&](int row, int buf) {
        const float4* src = (const float4*)(g_vote + (size_t)row * VOTE_PER_B);
        const uint32_t dst = sb + buf * (ROW_FLOATS * 4);
#pragma unroll
        for (int j = 0; j < 7; j++) {
            int idx = tid + j * 800;             // 5600 float4 total
            CP_ASYNC(dst + idx * 16, src + idx);
        }
        CP_COMMIT();
    };

    prefetch(blockIdx.x, 0);
    int buf = 0;

    for (int r = blockIdx.x; r < BSZ; r += ROUT_GRID) {
        if (r + ROUT_GRID < BSZ) {
            prefetch(r + ROUT_GRID, buf ^ 1);
            CP_WAIT(1);
        } else {
            CP_WAIT(0);
        }
        __syncthreads();

        float a_r[N_ROUTES];
#pragma unroll
        for (int nn = 0; nn < N_ROUTES; nn++)
            a_r[nn] = prim_act[(size_t)r * N_ROUTES + nn];

        float4 v[N_ROUTES];
        {
            const float* vb = s_vote + buf * ROW_FLOATS + m * MC_DIM + lane * 4;
#pragma unroll
            for (int nn = 0; nn < N_ROUTES; nn++)
                v[nn] = *(const float4*)(vb + nn * COLS);
        }

        float4 p = make_float4(0.f, 0.f, 0.f, 0.f);
#pragma unroll
        for (int nn = 0; nn < N_ROUTES; nn++) {
            p.x += a_r[nn] * v[nn].x;
            p.y += a_r[nn] * v[nn].y;
            p.z += a_r[nn] * v[nn].z;
            p.w += a_r[nn] * v[nn].w;
        }
        p.x *= (1.f / 25.f); p.y *= (1.f / 25.f);
        p.z *= (1.f / 25.f); p.w *= (1.f / 25.f);

        auto layernorm = [&](float4& x) {
            float s1 = x.x + x.y + x.z + x.w;
            float s2 = x.x * x.x + x.y * x.y + x.z * x.z + x.w * x.w;
            warp_sum2(s1, s2);
            float mu = s1 * (1.f / MC_DIM);
            float ve = s2 * (1.f / MC_DIM) - mu * mu + 1e-5f;
            float rr = rsqrtf(ve);
            rr = rr * (1.5f - 0.5f * ve * rr * rr);
            x.x = (x.x - mu) * rr * g4.x + b4.x;
            x.y = (x.y - mu) * rr * g4.y + b4.y;
            x.z = (x.z - mu) * rr * g4.z + b4.z;
            x.w = (x.w - mu) * rr * g4.w + b4.w;
        };
        layernorm(p);

        const float scale = 0.08838834764831845f;   // 1/sqrt(128)
#pragma unroll
        for (int it = 1; it <= 2; it++) {
#pragma unroll
            for (int nn = 0; nn < N_ROUTES; nn++) {
                float d = v[nn].x * p.x + v[nn].y * p.y + v[nn].z * p.z + v[nn].w * p.w;
                d = warp_sum(d);
                if (lane == 0) s_agree[nn * KCLS + m] = d * scale;
            }
            __syncthreads();

            if (m < N_ROUTES) {
                float aval = (lane < KCLS) ? s_agree[m * KCLS + lane] : -1e30f;
                float mx = warp_max32(aval);
                float e = (lane < KCLS) ? expf(aval - mx) : 0.f;
                float s = warp_sum(e);
                if (lane < KCLS) s_coef[m * KCLS + lane] = e / s;
            }
            __syncthreads();

            if (it == 2 && tid < N_ROUTES * KCLS)
                out_coef[(size_t)r * (N_ROUTES * KCLS) + tid] = s_coef[tid];

            p = make_float4(0.f, 0.f, 0.f, 0.f);
#pragma unroll
            for (int nn = 0; nn < N_ROUTES; nn++) {
                float ca = s_coef[nn * KCLS + m] * a_r[nn];
                p.x += ca * v[nn].x;
                p.y += ca * v[nn].y;
                p.z += ca * v[nn].z;
                p.w += ca * v[nn].w;
            }
            layernorm(p);
            __syncthreads();
        }

        {
            float d = p.x * em.x + p.y * em.y + p.z * em.z + p.w * em.w;
            d = warp_sum(d);
            if (lane == 0) out_logits[(size_t)r * KCLS + m] = d + bi;
        }
        if (tid < N_ROUTES)
            out_act[(size_t)r * N_ROUTES + tid] = a_r[tid];

        buf ^= 1;
        __syncthreads();
    }
}

// ---------------------------------------------------------------------------
extern "C" void kernel_launch(void* const* d_in, const int* in_sizes, int n_in,
                              void* d_out, int out_size) {
    const float* prim_pose = (const float*)d_in[0];
    const float* prim_act  = (const float*)d_in[1];
    const float* w         = (const float*)d_in[2];
    const float* ln_gamma  = (const float*)d_in[3];
    const float* ln_beta   = (const float*)d_in[4];
    const float* embedding = (const float*)d_in[5];
    const float* bias      = (const float*)d_in[6];

    float* out        = (float*)d_out;
    float* out_logits = out;
    float* out_act    = out + (size_t)BSZ * KCLS;
    float* out_coef   = out_act + (size_t)BSZ * N_ROUTES;

    prep_p_kernel<<<(BSZ * PP_STRIDE) / 4 / 512, 512>>>(prim_pose);
    prep_w_kernel<<<dim3(COLS / 32, PC_DIM / 32, N_ROUTES), dim3(32, 8)>>>(w);

    cudaFuncSetAttribute(vote_gemm_tc,
                         cudaFuncAttributeMaxDynamicSharedMemorySize, GEMM_SMEM);
    dim3 g(COLS / 128, BSZ / 128, N_ROUTES);   // (25, 32, 7)
    vote_gemm_tc<<<g, 256, GEMM_SMEM>>>();

    cudaFuncSetAttribute(routing_kernel,
                         cudaFuncAttributeMaxDynamicSharedMemorySize, ROUT_SMEM);
    routing_kernel<<<ROUT_GRID, 800, ROUT_SMEM>>>(prim_act, ln_gamma, ln_beta,
                                                  embedding, bias,
                                                  out_logits, out_act, out_coef);
}

// round 16
// speedup vs baseline: 1.3716x; 1.0018x over previous
#include <cuda_runtime.h>
#include <cuda_fp16.h>
#include <stdint.h>
#include <math.h>

#define N_ROUTES 7
#define PC_DIM   512
#define MC_DIM   128
#define KCLS     25
#define BSZ      4096
#define COLS     (KCLS * MC_DIM)        // 3200
#define VOTE_PER_B (N_ROUTES * COLS)    // 22400
#define PP_STRIDE (N_ROUTES * PC_DIM)   // 3584

__device__ float g_vote[(size_t)BSZ * VOTE_PER_B];                    // 367 MB
__device__ __half g_Ph[(size_t)BSZ * PP_STRIDE];                      // P fp16
__device__ __half g_Whi[(size_t)N_ROUTES * COLS * PC_DIM];            // [n][col][d]
__device__ __half g_Wlo[(size_t)N_ROUTES * COLS * PC_DIM];

__device__ __forceinline__ uint32_t smem_to_u32(const void* p) {
    uint32_t a;
    asm("{ .reg .u64 t; cvta.to.shared.u64 t, %1; cvt.u32.u64 %0, t; }"
        : "=r"(a) : "l"(p));
    return a;
}
__device__ __forceinline__ uint32_t usw64(uint32_t o) {     // SW64 swizzle
    return o ^ ((o >> 3) & 0x30);
}

#define CP_ASYNC(sa, ga) \
    asm volatile("cp.async.cg.shared.global [%0], [%1], 16;" :: "r"(sa), "l"(ga))
#define CP_COMMIT() asm volatile("cp.async.commit_group;" ::: "memory")
#define CP_WAIT(N)  asm volatile("cp.async.wait_group %0;" :: "n"(N))

// ---------------------------------------------------------------------------
// Prep 1: prim_pose -> fp16 (single digit)
// ---------------------------------------------------------------------------
__global__ __launch_bounds__(512) void prep_p_kernel(const float* __restrict__ P) {
    size_t i = (size_t)blockIdx.x * 512 + threadIdx.x;   // float4 index
    float4 x = ((const float4*)P)[i];
    __half2* dh = (__half2*)g_Ph;
    dh[2 * i]     = __halves2half2(__float2half(x.x), __float2half(x.y));
    dh[2 * i + 1] = __halves2half2(__float2half(x.z), __float2half(x.w));
}

// ---------------------------------------------------------------------------
// Prep 2: transpose+split W[n][d][col] -> Whi/Wlo [n][col][d] (fp16 digits)
// ---------------------------------------------------------------------------
__global__ __launch_bounds__(256) void prep_w_kernel(const float* __restrict__ W) {
    __shared__ float tile[32][33];
    const int n = blockIdx.z;
    const int c0 = blockIdx.x * 32;
    const int d0 = blockIdx.y * 32;
    const float* Wn = W + (size_t)n * PC_DIM * COLS;
#pragma unroll
    for (int j = 0; j < 4; j++) {
        int d = d0 + threadIdx.y + j * 8;
        tile[threadIdx.y + j * 8][threadIdx.x] = Wn[(size_t)d * COLS + c0 + threadIdx.x];
    }
    __syncthreads();
#pragma unroll
    for (int j = 0; j < 4; j++) {
        int col = c0 + threadIdx.y + j * 8;
        int d = d0 + threadIdx.x;
        float x = tile[threadIdx.x][threadIdx.y + j * 8];
        __half h = __float2half(x);
        size_t o = ((size_t)n * COLS + col) * PC_DIM + d;
        g_Whi[o] = h;
        g_Wlo[o] = __float2half(x - __half2float(h));
    }
}

// ---------------------------------------------------------------------------
// Vote GEMM (R15, proven): P fp16 x (Whi + Wlo) = 2 MMAs per step.
// CTA 128x128, 8 warps (4 wm x 2 wn, warp tile 32x64). KCH=32, SW64 smem,
// 3-stage cp.async.
// ---------------------------------------------------------------------------
#define KCH 32
#define T_A  0
#define T_BH 8192
#define T_BL 16384
#define STG_BYTES 24576
#define NSTG 3
#define GEMM_SMEM (NSTG * STG_BYTES)      // 73728 -> 2 CTAs/SM
#define NC (PC_DIM / KCH)                 // 16

#define LDSM_X4(r0, r1, r2, r3, a) \
    asm volatile("ldmatrix.sync.aligned.m8n8.x4.shared.b16 {%0,%1,%2,%3}, [%4];" \
        : "=r"(r0), "=r"(r1), "=r"(r2), "=r"(r3) : "r"(a))

#define MMA_F16(d, a, b0, b1) \
    asm volatile("mma.sync.aligned.m16n8k16.row.col.f32.f16.f16.f32 " \
        "{%0,%1,%2,%3}, {%4,%5,%6,%7}, {%8,%9}, {%0,%1,%2,%3};" \
        : "+f"((d)[0]), "+f"((d)[1]), "+f"((d)[2]), "+f"((d)[3]) \
        : "r"((a)[0]), "r"((a)[1]), "r"((a)[2]), "r"((a)[3]), "r"(b0), "r"(b1))

__global__ __launch_bounds__(256, 2) void vote_gemm_tc(void) {
    extern __shared__ char smem[];
    const uint32_t sb = smem_to_u32(smem);
    const int tid  = threadIdx.x;
    const int lane = tid & 31;
    const int warp = tid >> 5;
    const int wm   = warp & 3;          // M block of 32
    const int wn   = warp >> 2;         // N block of 64

    const int n  = blockIdx.z;
    const int bm = blockIdx.y * 128;
    const int bn = blockIdx.x * 128;

    const __half* A   = g_Ph  + (size_t)bm * PP_STRIDE + (size_t)n * PC_DIM;
    const __half* Bhi = g_Whi + ((size_t)n * COLS + bn) * PC_DIM;
    const __half* Blo = g_Wlo + ((size_t)n * COLS + bn) * PC_DIM;

    float acc[2][8][4];
#pragma unroll
    for (int i = 0; i < 2; i++)
#pragma unroll
        for (int j = 0; j < 8; j++)
#pragma unroll
            for (int q = 0; q < 4; q++) acc[i][j][q] = 0.f;

    const int lrow = lane & 15, lch = lane >> 4;

    // 1536 16B-chunks/stage, 6 per thread; t = 0:A, 1:Bh, 2:Bl
    auto issue_stage = [&](int c, int buf) {
        const int k0 = c * KCH;
        const uint32_t sbase = sb + buf * STG_BYTES;
#pragma unroll
        for (int p = 0; p < 6; p++) {
            int id  = p * 256 + tid;
            int t   = id >> 9;          // 0..2
            int rem = id & 511;
            int row = rem >> 2;
            int ch  = rem & 3;
            uint32_t sa = sbase + t * 8192 + usw64(row * 64 + ch * 16);
            const __half* g;
            if (t == 0)      g = A   + (size_t)row * PP_STRIDE + k0 + ch * 8;
            else if (t == 1) g = Bhi + (size_t)row * PC_DIM + k0 + ch * 8;
            else             g = Blo + (size_t)row * PC_DIM + k0 + ch * 8;
            CP_ASYNC(sa, g);
        }
        CP_COMMIT();
    };

    issue_stage(0, 0);
    issue_stage(1, 1);
    issue_stage(2, 2);

    for (int c = 0; c < NC; c++) {
        if (c <= NC - 3)      CP_WAIT(2);
        else if (c == NC - 2) CP_WAIT(1);
        else                  CP_WAIT(0);
        __syncthreads();

        const uint32_t sbase = sb + (c % 3) * STG_BYTES;
#pragma unroll
        for (int ks = 0; ks < 2; ks++) {
            const uint32_t kb = ks * 32 + lch * 16;
            uint32_t ah[2][4];
#pragma unroll
            for (int mt = 0; mt < 2; mt++) {
                uint32_t ao = usw64((wm * 32 + mt * 16 + lrow) * 64 + kb);
                LDSM_X4(ah[mt][0], ah[mt][1], ah[mt][2], ah[mt][3], sbase + T_A + ao);
            }
#pragma unroll
            for (int g = 0; g < 4; g++) {
                uint32_t bo = usw64((wn * 64 + g * 16 + lrow) * 64 + kb);
                uint32_t bh[4], bl[4];
                LDSM_X4(bh[0], bh[1], bh[2], bh[3], sbase + T_BH + bo);
                LDSM_X4(bl[0], bl[1], bl[2], bl[3], sbase + T_BL + bo);
                MMA_F16(acc[0][g * 2 + 0], ah[0], bh[0], bh[2]);
                MMA_F16(acc[0][g * 2 + 1], ah[0], bh[1], bh[3]);
                MMA_F16(acc[1][g * 2 + 0], ah[1], bh[0], bh[2]);
                MMA_F16(acc[1][g * 2 + 1], ah[1], bh[1], bh[3]);
                MMA_F16(acc[0][g * 2 + 0], ah[0], bl[0], bl[2]);
                MMA_F16(acc[0][g * 2 + 1], ah[0], bl[1], bl[3]);
                MMA_F16(acc[1][g * 2 + 0], ah[1], bl[0], bl[2]);
                MMA_F16(acc[1][g * 2 + 1], ah[1], bl[1], bl[3]);
            }
        }
        __syncthreads();
        if (c + 3 < NC) issue_stage(c + 3, (c + 3) % 3);
    }

    // epilogue: direct fp32 stores
#pragma unroll
    for (int mt = 0; mt < 2; mt++) {
#pragma unroll
        for (int j = 0; j < 8; j++) {
            int g = j >> 1, nt = j & 1;
            int row = bm + wm * 32 + mt * 16 + (lane >> 2);
            int col = bn + wn * 64 + g * 16 + nt * 8 + (lane & 3) * 2;
            float* d0 = g_vote + (size_t)row * VOTE_PER_B + (size_t)n * COLS + col;
            float* d1 = d0 + (size_t)8 * VOTE_PER_B;
            *(float2*)d0 = make_float2(acc[mt][j][0], acc[mt][j][1]);
            *(float2*)d1 = make_float2(acc[mt][j][2], acc[mt][j][3]);
        }
    }
}

// ---------------------------------------------------------------------------
// Persistent routing: 296 CTAs, 800 threads, double-buffered cp.async vote
// prefetch. Warp = capsule m. Iteration-end barrier elided (s_coef reads are
// ordered against the next softmax's writes by the next post-agree barrier).
// ---------------------------------------------------------------------------
#define ROUT_GRID 296
#define ROW_FLOATS VOTE_PER_B                    // 22400
#define ROUT_SMEM (2 * ROW_FLOATS * 4)           // 179200 bytes

__device__ __forceinline__ float warp_sum(float v) {
#pragma unroll
    for (int o = 16; o; o >>= 1) v += __shfl_xor_sync(0xffffffffu, v, o);
    return v;
}
__device__ __forceinline__ float warp_max32(float v) {
#pragma unroll
    for (int o = 16; o; o >>= 1) v = fmaxf(v, __shfl_xor_sync(0xffffffffu, v, o));
    return v;
}
__device__ __forceinline__ void warp_sum2(float& a, float& b) {
#pragma unroll
    for (int o = 16; o; o >>= 1) {
        a += __shfl_xor_sync(0xffffffffu, a, o);
        b += __shfl_xor_sync(0xffffffffu, b, o);
    }
}

__global__ __launch_bounds__(800, 1) void routing_kernel(
    const float* __restrict__ prim_act,
    const float* __restrict__ ln_gamma, const float* __restrict__ ln_beta,
    const float* __restrict__ embedding, const float* __restrict__ bias,
    float* __restrict__ out_logits, float* __restrict__ out_act,
    float* __restrict__ out_coef) {
    extern __shared__ float s_vote[];            // 2 x 22400 floats
    __shared__ float s_agree[N_ROUTES * KCLS];
    __shared__ float s_coef[N_ROUTES * KCLS];

    const int tid  = threadIdx.x;
    const int lane = tid & 31;
    const int m    = tid >> 5;                   // warp id == capsule, 0..24
    const uint32_t sb = smem_to_u32(s_vote);

    const float4 g4 = ((const float4*)ln_gamma)[lane];
    const float4 b4 = ((const float4*)ln_beta)[lane];
    const float4 em = ((const float4*)(embedding + (size_t)m * MC_DIM))[lane];
    const float  bi = bias[m];

    auto prefetch = [&](int row, int buf) {
        const float4* src = (const float4*)(g_vote + (size_t)row * VOTE_PER_B);
        const uint32_t dst = sb + buf * (ROW_FLOATS * 4);
#pragma unroll
        for (int j = 0; j < 7; j++) {
            int idx = tid + j * 800;             // 5600 float4 total
            CP_ASYNC(dst + idx * 16, src + idx);
        }
        CP_COMMIT();
    };

    prefetch(blockIdx.x, 0);
    int buf = 0;

    for (int r = blockIdx.x; r < BSZ; r += ROUT_GRID) {
        if (r + ROUT_GRID < BSZ) {
            prefetch(r + ROUT_GRID, buf ^ 1);
            CP_WAIT(1);
        } else {
            CP_WAIT(0);
        }
        __syncthreads();

        float a_r[N_ROUTES];
#pragma unroll
        for (int nn = 0; nn < N_ROUTES; nn++)
            a_r[nn] = prim_act[(size_t)r * N_ROUTES + nn];

        float4 v[N_ROUTES];
        {
            const float* vb = s_vote + buf * ROW_FLOATS + m * MC_DIM + lane * 4;
#pragma unroll
            for (int nn = 0; nn < N_ROUTES; nn++)
                v[nn] = *(const float4*)(vb + nn * COLS);
        }

        float4 p = make_float4(0.f, 0.f, 0.f, 0.f);
#pragma unroll
        for (int nn = 0; nn < N_ROUTES; nn++) {
            p.x += a_r[nn] * v[nn].x;
            p.y += a_r[nn] * v[nn].y;
            p.z += a_r[nn] * v[nn].z;
            p.w += a_r[nn] * v[nn].w;
        }
        p.x *= (1.f / 25.f); p.y *= (1.f / 25.f);
        p.z *= (1.f / 25.f); p.w *= (1.f / 25.f);

        auto layernorm = [&](float4& x) {
            float s1 = x.x + x.y + x.z + x.w;
            float s2 = x.x * x.x + x.y * x.y + x.z * x.z + x.w * x.w;
            warp_sum2(s1, s2);
            float mu = s1 * (1.f / MC_DIM);
            float ve = s2 * (1.f / MC_DIM) - mu * mu + 1e-5f;
            float rr = rsqrtf(ve);
            rr = rr * (1.5f - 0.5f * ve * rr * rr);
            x.x = (x.x - mu) * rr * g4.x + b4.x;
            x.y = (x.y - mu) * rr * g4.y + b4.y;
            x.z = (x.z - mu) * rr * g4.z + b4.z;
            x.w = (x.w - mu) * rr * g4.w + b4.w;
        };
        layernorm(p);

        const float scale = 0.08838834764831845f;   // 1/sqrt(128)
#pragma unroll
        for (int it = 1; it <= 2; it++) {
            // agree[n][m] = dot(v[n], p) * scale
#pragma unroll
            for (int nn = 0; nn < N_ROUTES; nn++) {
                float d = v[nn].x * p.x + v[nn].y * p.y + v[nn].z * p.z + v[nn].w * p.w;
                d = warp_sum(d);
                if (lane == 0) s_agree[nn * KCLS + m] = d * scale;
            }
            __syncthreads();    // agree visible; also orders prior-it coef reads
                                // before this softmax's coef writes

            if (m < N_ROUTES) {
                float aval = (lane < KCLS) ? s_agree[m * KCLS + lane] : -1e30f;
                float mx = warp_max32(aval);
                float e = (lane < KCLS) ? expf(aval - mx) : 0.f;
                float s = warp_sum(e);
                if (lane < KCLS) s_coef[m * KCLS + lane] = e / s;
            }
            __syncthreads();    // coef visible to all warps

            if (it == 2 && tid < N_ROUTES * KCLS)
                out_coef[(size_t)r * (N_ROUTES * KCLS) + tid] = s_coef[tid];

            p = make_float4(0.f, 0.f, 0.f, 0.f);
#pragma unroll
            for (int nn = 0; nn < N_ROUTES; nn++) {
                float ca = s_coef[nn * KCLS + m] * a_r[nn];
                p.x += ca * v[nn].x;
                p.y += ca * v[nn].y;
                p.z += ca * v[nn].z;
                p.w += ca * v[nn].w;
            }
            layernorm(p);
            // NOTE: no barrier here — next iteration's post-agree barrier
            // orders these s_coef reads against the next s_coef writes.
        }

        {
            float d = p.x * em.x + p.y * em.y + p.z * em.z + p.w * em.w;
            d = warp_sum(d);
            if (lane == 0) out_logits[(size_t)r * KCLS + m] = d + bi;
        }
        if (tid < N_ROUTES)
            out_act[(size_t)r * N_ROUTES + tid] = a_r[tid];

        buf ^= 1;
        __syncthreads();    // row-end: all smem reads done before re-prefetch
    }
}

// ---------------------------------------------------------------------------
// Launch: preps forked across two streams (event fork/join, capture-legal),
// then GEMM -> routing sequential on the capture-origin stream.
// ---------------------------------------------------------------------------
extern "C" void kernel_launch(void* const* d_in, const int* in_sizes, int n_in,
                              void* d_out, int out_size) {
    const float* prim_pose = (const float*)d_in[0];
    const float* prim_act  = (const float*)d_in[1];
    const float* w         = (const float*)d_in[2];
    const float* ln_gamma  = (const float*)d_in[3];
    const float* ln_beta   = (const float*)d_in[4];
    const float* embedding = (const float*)d_in[5];
    const float* bias      = (const float*)d_in[6];

    float* out        = (float*)d_out;
    float* out_logits = out;
    float* out_act    = out + (size_t)BSZ * KCLS;
    float* out_coef   = out_act + (size_t)BSZ * N_ROUTES;

    static cudaStream_t s1 = nullptr;
    static cudaEvent_t evRoot, evP;
    if (s1 == nullptr) {
        cudaStreamCreateWithFlags(&s1, cudaStreamNonBlocking);
        cudaEventCreateWithFlags(&evRoot, cudaEventDisableTiming);
        cudaEventCreateWithFlags(&evP, cudaEventDisableTiming);
        cudaFuncSetAttribute(vote_gemm_tc,
                             cudaFuncAttributeMaxDynamicSharedMemorySize, GEMM_SMEM);
        cudaFuncSetAttribute(routing_kernel,
                             cudaFuncAttributeMaxDynamicSharedMemorySize, ROUT_SMEM);
    }

    // fork: prep_p on s1, prep_w on the origin stream
    cudaEventRecord(evRoot, 0);
    cudaStreamWaitEvent(s1, evRoot, 0);
    prep_p_kernel<<<(BSZ * PP_STRIDE) / 4 / 512, 512, 0, s1>>>(prim_pose);
    cudaEventRecord(evP, s1);
    prep_w_kernel<<<dim3(COLS / 32, PC_DIM / 32, N_ROUTES), dim3(32, 8), 0, 0>>>(w);
    cudaStreamWaitEvent(0, evP, 0);   // join before GEMM

    dim3 g(COLS / 128, BSZ / 128, N_ROUTES);   // (25, 32, 7)
    vote_gemm_tc<<<g, 256, GEMM_SMEM>>>();

    routing_kernel<<<ROUT_GRID, 800, ROUT_SMEM>>>(prim_act, ln_gamma, ln_beta,
                                                  embedding, bias,
                                                  out_logits, out_act, out_coef);
}

// round 17
// speedup vs baseline: 1.3729x; 1.0009x over previous
#include <cuda_runtime.h>
#include <cuda_fp16.h>
#include <stdint.h>
#include <math.h>

#define N_ROUTES 7
#define PC_DIM   512
#define MC_DIM   128
#define KCLS     25
#define BSZ      4096
#define COLS     (KCLS * MC_DIM)        // 3200
#define VOTE_PER_B (N_ROUTES * COLS)    // 22400
#define PP_STRIDE (N_ROUTES * PC_DIM)   // 3584

__device__ float g_vote[(size_t)BSZ * VOTE_PER_B];                    // 367 MB
__device__ __half g_Ph[(size_t)BSZ * PP_STRIDE];                      // P fp16
__device__ __half g_Whi[(size_t)N_ROUTES * COLS * PC_DIM];            // [n][col][d]
__device__ __half g_Wlo[(size_t)N_ROUTES * COLS * PC_DIM];

__device__ __forceinline__ uint32_t smem_to_u32(const void* p) {
    uint32_t a;
    asm("{ .reg .u64 t; cvta.to.shared.u64 t, %1; cvt.u32.u64 %0, t; }"
        : "=r"(a) : "l"(p));
    return a;
}
__device__ __forceinline__ uint32_t usw64(uint32_t o) {     // SW64 swizzle
    return o ^ ((o >> 3) & 0x30);
}

#define CP_ASYNC(sa, ga) \
    asm volatile("cp.async.cg.shared.global [%0], [%1], 16;" :: "r"(sa), "l"(ga))
#define CP_COMMIT() asm volatile("cp.async.commit_group;" ::: "memory")
#define CP_WAIT(N)  asm volatile("cp.async.wait_group %0;" :: "n"(N))

// ---------------------------------------------------------------------------
// Prep 1: prim_pose -> fp16 (single digit)
// ---------------------------------------------------------------------------
__global__ __launch_bounds__(512) void prep_p_kernel(const float* __restrict__ P) {
    size_t i = (size_t)blockIdx.x * 512 + threadIdx.x;   // float4 index
    float4 x = ((const float4*)P)[i];
    __half2* dh = (__half2*)g_Ph;
    dh[2 * i]     = __halves2half2(__float2half(x.x), __float2half(x.y));
    dh[2 * i + 1] = __halves2half2(__float2half(x.z), __float2half(x.w));
}

// ---------------------------------------------------------------------------
// Prep 2: transpose+split W[n][d][col] -> Whi/Wlo [n][col][d] (fp16 digits)
// ---------------------------------------------------------------------------
__global__ __launch_bounds__(256) void prep_w_kernel(const float* __restrict__ W) {
    __shared__ float tile[32][33];
    const int n = blockIdx.z;
    const int c0 = blockIdx.x * 32;
    const int d0 = blockIdx.y * 32;
    const float* Wn = W + (size_t)n * PC_DIM * COLS;
#pragma unroll
    for (int j = 0; j < 4; j++) {
        int d = d0 + threadIdx.y + j * 8;
        tile[threadIdx.y + j * 8][threadIdx.x] = Wn[(size_t)d * COLS + c0 + threadIdx.x];
    }
    __syncthreads();
#pragma unroll
    for (int j = 0; j < 4; j++) {
        int col = c0 + threadIdx.y + j * 8;
        int d = d0 + threadIdx.x;
        float x = tile[threadIdx.x][threadIdx.y + j * 8];
        __half h = __float2half(x);
        size_t o = ((size_t)n * COLS + col) * PC_DIM + d;
        g_Whi[o] = h;
        g_Wlo[o] = __float2half(x - __half2float(h));
    }
}

// ---------------------------------------------------------------------------
// Vote GEMM (R15 core): P fp16 x (Whi + Wlo) = 2 MMAs per step.
// CTA 128x128, 8 warps (4 wm x 2 wn, warp tile 32x64). KCH=32, SW64 smem,
// 3-stage cp.async. Epilogue uses streaming stores (vote is write-once,
// read-once — keep W digit tiles resident in L2 instead).
// ---------------------------------------------------------------------------
#define KCH 32
#define T_A  0
#define T_BH 8192
#define T_BL 16384
#define STG_BYTES 24576
#define NSTG 3
#define GEMM_SMEM (NSTG * STG_BYTES)      // 73728 -> 2 CTAs/SM
#define NC (PC_DIM / KCH)                 // 16

#define LDSM_X4(r0, r1, r2, r3, a) \
    asm volatile("ldmatrix.sync.aligned.m8n8.x4.shared.b16 {%0,%1,%2,%3}, [%4];" \
        : "=r"(r0), "=r"(r1), "=r"(r2), "=r"(r3) : "r"(a))

#define MMA_F16(d, a, b0, b1) \
    asm volatile("mma.sync.aligned.m16n8k16.row.col.f32.f16.f16.f32 " \
        "{%0,%1,%2,%3}, {%4,%5,%6,%7}, {%8,%9}, {%0,%1,%2,%3};" \
        : "+f"((d)[0]), "+f"((d)[1]), "+f"((d)[2]), "+f"((d)[3]) \
        : "r"((a)[0]), "r"((a)[1]), "r"((a)[2]), "r"((a)[3]), "r"(b0), "r"(b1))

__global__ __launch_bounds__(256, 2) void vote_gemm_tc(void) {
    extern __shared__ char smem[];
    const uint32_t sb = smem_to_u32(smem);
    const int tid  = threadIdx.x;
    const int lane = tid & 31;
    const int warp = tid >> 5;
    const int wm   = warp & 3;          // M block of 32
    const int wn   = warp >> 2;         // N block of 64

    const int n  = blockIdx.z;
    const int bm = blockIdx.y * 128;
    const int bn = blockIdx.x * 128;

    const __half* A   = g_Ph  + (size_t)bm * PP_STRIDE + (size_t)n * PC_DIM;
    const __half* Bhi = g_Whi + ((size_t)n * COLS + bn) * PC_DIM;
    const __half* Blo = g_Wlo + ((size_t)n * COLS + bn) * PC_DIM;

    float acc[2][8][4];
#pragma unroll
    for (int i = 0; i < 2; i++)
#pragma unroll
        for (int j = 0; j < 8; j++)
#pragma unroll
            for (int q = 0; q < 4; q++) acc[i][j][q] = 0.f;

    const int lrow = lane & 15, lch = lane >> 4;

    // 1536 16B-chunks/stage, 6 per thread; t = 0:A, 1:Bh, 2:Bl
    auto issue_stage = [&](int c, int buf) {
        const int k0 = c * KCH;
        const uint32_t sbase = sb + buf * STG_BYTES;
#pragma unroll
        for (int p = 0; p < 6; p++) {
            int id  = p * 256 + tid;
            int t   = id >> 9;          // 0..2
            int rem = id & 511;
            int row = rem >> 2;
            int ch  = rem & 3;
            uint32_t sa = sbase + t * 8192 + usw64(row * 64 + ch * 16);
            const __half* g;
            if (t == 0)      g = A   + (size_t)row * PP_STRIDE + k0 + ch * 8;
            else if (t == 1) g = Bhi + (size_t)row * PC_DIM + k0 + ch * 8;
            else             g = Blo + (size_t)row * PC_DIM + k0 + ch * 8;
            CP_ASYNC(sa, g);
        }
        CP_COMMIT();
    };

    issue_stage(0, 0);
    issue_stage(1, 1);
    issue_stage(2, 2);

    for (int c = 0; c < NC; c++) {
        if (c <= NC - 3)      CP_WAIT(2);
        else if (c == NC - 2) CP_WAIT(1);
        else                  CP_WAIT(0);
        __syncthreads();

        const uint32_t sbase = sb + (c % 3) * STG_BYTES;
#pragma unroll
        for (int ks = 0; ks < 2; ks++) {
            const uint32_t kb = ks * 32 + lch * 16;
            uint32_t ah[2][4];
#pragma unroll
            for (int mt = 0; mt < 2; mt++) {
                uint32_t ao = usw64((wm * 32 + mt * 16 + lrow) * 64 + kb);
                LDSM_X4(ah[mt][0], ah[mt][1], ah[mt][2], ah[mt][3], sbase + T_A + ao);
            }
#pragma unroll
            for (int g = 0; g < 4; g++) {
                uint32_t bo = usw64((wn * 64 + g * 16 + lrow) * 64 + kb);
                uint32_t bh[4], bl[4];
                LDSM_X4(bh[0], bh[1], bh[2], bh[3], sbase + T_BH + bo);
                LDSM_X4(bl[0], bl[1], bl[2], bl[3], sbase + T_BL + bo);
                MMA_F16(acc[0][g * 2 + 0], ah[0], bh[0], bh[2]);
                MMA_F16(acc[0][g * 2 + 1], ah[0], bh[1], bh[3]);
                MMA_F16(acc[1][g * 2 + 0], ah[1], bh[0], bh[2]);
                MMA_F16(acc[1][g * 2 + 1], ah[1], bh[1], bh[3]);
                MMA_F16(acc[0][g * 2 + 0], ah[0], bl[0], bl[2]);
                MMA_F16(acc[0][g * 2 + 1], ah[0], bl[1], bl[3]);
                MMA_F16(acc[1][g * 2 + 0], ah[1], bl[0], bl[2]);
                MMA_F16(acc[1][g * 2 + 1], ah[1], bl[1], bl[3]);
            }
        }
        __syncthreads();
        if (c + 3 < NC) issue_stage(c + 3, (c + 3) % 3);
    }

    // epilogue: streaming fp32 stores (write-once data; don't pollute L2)
#pragma unroll
    for (int mt = 0; mt < 2; mt++) {
#pragma unroll
        for (int j = 0; j < 8; j++) {
            int g = j >> 1, nt = j & 1;
            int row = bm + wm * 32 + mt * 16 + (lane >> 2);
            int col = bn + wn * 64 + g * 16 + nt * 8 + (lane & 3) * 2;
            float2* d0 = (float2*)(g_vote + (size_t)row * VOTE_PER_B
                                   + (size_t)n * COLS + col);
            float2* d1 = (float2*)((float*)d0 + (size_t)8 * VOTE_PER_B);
            __stcs(d0, make_float2(acc[mt][j][0], acc[mt][j][1]));
            __stcs(d1, make_float2(acc[mt][j][2], acc[mt][j][3]));
        }
    }
}

// ---------------------------------------------------------------------------
// Persistent routing: 148 CTAs (single wave), 800 threads, double-buffered
// cp.async vote prefetch. Warp = capsule m. LN uses plain MUFU rsqrt.
// ---------------------------------------------------------------------------
#define ROUT_GRID 148
#define ROW_FLOATS VOTE_PER_B                    // 22400
#define ROUT_SMEM (2 * ROW_FLOATS * 4)           // 179200 bytes

__device__ __forceinline__ float warp_sum(float v) {
#pragma unroll
    for (int o = 16; o; o >>= 1) v += __shfl_xor_sync(0xffffffffu, v, o);
    return v;
}
__device__ __forceinline__ float warp_max32(float v) {
#pragma unroll
    for (int o = 16; o; o >>= 1) v = fmaxf(v, __shfl_xor_sync(0xffffffffu, v, o));
    return v;
}
__device__ __forceinline__ void warp_sum2(float& a, float& b) {
#pragma unroll
    for (int o = 16; o; o >>= 1) {
        a += __shfl_xor_sync(0xffffffffu, a, o);
        b += __shfl_xor_sync(0xffffffffu, b, o);
    }
}

__global__ __launch_bounds__(800, 1) void routing_kernel(
    const float* __restrict__ prim_act,
    const float* __restrict__ ln_gamma, const float* __restrict__ ln_beta,
    const float* __restrict__ embedding, const float* __restrict__ bias,
    float* __restrict__ out_logits, float* __restrict__ out_act,
    float* __restrict__ out_coef) {
    extern __shared__ float s_vote[];            // 2 x 22400 floats
    __shared__ float s_agree[N_ROUTES * KCLS];
    __shared__ float s_coef[N_ROUTES * KCLS];

    const int tid  = threadIdx.x;
    const int lane = tid & 31;
    const int m    = tid >> 5;                   // warp id == capsule, 0..24
    const uint32_t sb = smem_to_u32(s_vote);

    const float4 g4 = ((const float4*)ln_gamma)[lane];
    const float4 b4 = ((const float4*)ln_beta)[lane];
    const float4 em = ((const float4*)(embedding + (size_t)m * MC_DIM))[lane];
    const float  bi = bias[m];

    auto prefetch = [&](int row, int buf) {
        const float4* src = (const float4*)(g_vote + (size_t)row * VOTE_PER_B);
        const uint32_t dst = sb + buf * (ROW_FLOATS * 4);
#pragma unroll
        for (int j = 0; j < 7; j++) {
            int idx = tid + j * 800;             // 5600 float4 total
            CP_ASYNC(dst + idx * 16, src + idx);
        }
        CP_COMMIT();
    };

    prefetch(blockIdx.x, 0);
    int buf = 0;

    for (int r = blockIdx.x; r < BSZ; r += ROUT_GRID) {
        if (r + ROUT_GRID < BSZ) {
            prefetch(r + ROUT_GRID, buf ^ 1);
            CP_WAIT(1);
        } else {
            CP_WAIT(0);
        }
        __syncthreads();

        float a_r[N_ROUTES];
#pragma unroll
        for (int nn = 0; nn < N_ROUTES; nn++)
            a_r[nn] = prim_act[(size_t)r * N_ROUTES + nn];

        float4 v[N_ROUTES];
        {
            const float* vb = s_vote + buf * ROW_FLOATS + m * MC_DIM + lane * 4;
#pragma unroll
            for (int nn = 0; nn < N_ROUTES; nn++)
                v[nn] = *(const float4*)(vb + nn * COLS);
        }

        float4 p = make_float4(0.f, 0.f, 0.f, 0.f);
#pragma unroll
        for (int nn = 0; nn < N_ROUTES; nn++) {
            p.x += a_r[nn] * v[nn].x;
            p.y += a_r[nn] * v[nn].y;
            p.z += a_r[nn] * v[nn].z;
            p.w += a_r[nn] * v[nn].w;
        }
        p.x *= (1.f / 25.f); p.y *= (1.f / 25.f);
        p.z *= (1.f / 25.f); p.w *= (1.f / 25.f);

        auto layernorm = [&](float4& x) {
            float s1 = x.x + x.y + x.z + x.w;
            float s2 = x.x * x.x + x.y * x.y + x.z * x.z + x.w * x.w;
            warp_sum2(s1, s2);
            float mu = s1 * (1.f / MC_DIM);
            float ve = s2 * (1.f / MC_DIM) - mu * mu + 1e-5f;
            float rr = rsqrtf(ve);               // MUFU.RSQ: 2^-22 rel, plenty
            x.x = (x.x - mu) * rr * g4.x + b4.x;
            x.y = (x.y - mu) * rr * g4.y + b4.y;
            x.z = (x.z - mu) * rr * g4.z + b4.z;
            x.w = (x.w - mu) * rr * g4.w + b4.w;
        };
        layernorm(p);

        const float scale = 0.08838834764831845f;   // 1/sqrt(128)
#pragma unroll
        for (int it = 1; it <= 2; it++) {
#pragma unroll
            for (int nn = 0; nn < N_ROUTES; nn++) {
                float d = v[nn].x * p.x + v[nn].y * p.y + v[nn].z * p.z + v[nn].w * p.w;
                d = warp_sum(d);
                if (lane == 0) s_agree[nn * KCLS + m] = d * scale;
            }
            __syncthreads();    // agree visible; orders prior coef reads too

            if (m < N_ROUTES) {
                float aval = (lane < KCLS) ? s_agree[m * KCLS + lane] : -1e30f;
                float mx = warp_max32(aval);
                float e = (lane < KCLS) ? expf(aval - mx) : 0.f;
                float s = warp_sum(e);
                if (lane < KCLS) s_coef[m * KCLS + lane] = e / s;
            }
            __syncthreads();    // coef visible

            if (it == 2 && tid < N_ROUTES * KCLS)
                out_coef[(size_t)r * (N_ROUTES * KCLS) + tid] = s_coef[tid];

            p = make_float4(0.f, 0.f, 0.f, 0.f);
#pragma unroll
            for (int nn = 0; nn < N_ROUTES; nn++) {
                float ca = s_coef[nn * KCLS + m] * a_r[nn];
                p.x += ca * v[nn].x;
                p.y += ca * v[nn].y;
                p.z += ca * v[nn].z;
                p.w += ca * v[nn].w;
            }
            layernorm(p);
            // no barrier: next post-agree barrier orders s_coef reuse
        }

        {
            float d = p.x * em.x + p.y * em.y + p.z * em.z + p.w * em.w;
            d = warp_sum(d);
            if (lane == 0) out_logits[(size_t)r * KCLS + m] = d + bi;
        }
        if (tid < N_ROUTES)
            out_act[(size_t)r * N_ROUTES + tid] = a_r[tid];

        buf ^= 1;
        __syncthreads();    // all buffer reads done before its re-prefetch
    }
}

// ---------------------------------------------------------------------------
// Launch: preps forked across two streams, then GEMM -> routing.
// ---------------------------------------------------------------------------
extern "C" void kernel_launch(void* const* d_in, const int* in_sizes, int n_in,
                              void* d_out, int out_size) {
    const float* prim_pose = (const float*)d_in[0];
    const float* prim_act  = (const float*)d_in[1];
    const float* w         = (const float*)d_in[2];
    const float* ln_gamma  = (const float*)d_in[3];
    const float* ln_beta   = (const float*)d_in[4];
    const float* embedding = (const float*)d_in[5];
    const float* bias      = (const float*)d_in[6];

    float* out        = (float*)d_out;
    float* out_logits = out;
    float* out_act    = out + (size_t)BSZ * KCLS;
    float* out_coef   = out_act + (size_t)BSZ * N_ROUTES;

    static cudaStream_t s1 = nullptr;
    static cudaEvent_t evRoot, evP;
    if (s1 == nullptr) {
        cudaStreamCreateWithFlags(&s1, cudaStreamNonBlocking);
        cudaEventCreateWithFlags(&evRoot, cudaEventDisableTiming);
        cudaEventCreateWithFlags(&evP, cudaEventDisableTiming);
        cudaFuncSetAttribute(vote_gemm_tc,
                             cudaFuncAttributeMaxDynamicSharedMemorySize, GEMM_SMEM);
        cudaFuncSetAttribute(routing_kernel,
                             cudaFuncAttributeMaxDynamicSharedMemorySize, ROUT_SMEM);
    }

    cudaEventRecord(evRoot, 0);
    cudaStreamWaitEvent(s1, evRoot, 0);
    prep_p_kernel<<<(BSZ * PP_STRIDE) / 4 / 512, 512, 0, s1>>>(prim_pose);
    cudaEventRecord(evP, s1);
    prep_w_kernel<<<dim3(COLS / 32, PC_DIM / 32, N_ROUTES), dim3(32, 8), 0, 0>>>(w);
    cudaStreamWaitEvent(0, evP, 0);

    dim3 g(COLS / 128, BSZ / 128, N_ROUTES);   // (25, 32, 7)
    vote_gemm_tc<<<g, 256, GEMM_SMEM>>>();

    routing_kernel<<<ROUT_GRID, 800, ROUT_SMEM>>>(prim_act, ln_gamma, ln_beta,
                                                  embedding, bias,
                                                  out_logits, out_act, out_coef);
}